// round 16
// baseline (speedup 1.0000x reference)
#include <cuda_runtime.h>
#include <cuda_bf16.h>
#include <math.h>
#include <stdint.h>

#define LQ     4096
#define DMODEL 576
#define TD     1728
#define NHEAD  8
#define DHEAD  72
#define OUTC   128
#define DPAD   80

// ---------------- scratch ----------------
__device__ float g_x[LQ * DMODEL];
__device__ float g_o[LQ * DMODEL];
__device__ float g_z[LQ * OUTC];          // x @ cw^T
__device__ float g_m1t[OUTC * DMODEL];    // M1T[n][j] = sum_k cw[n][k] * wo[j][k]
__device__ float g_b2[OUTC];              // b_out @ cw^T
__device__ float g_wq[DMODEL * TD];
__device__ float g_wo[DMODEL * DMODEL];
__device__ float g_cw[OUTC * DMODEL];
__device__ __nv_bfloat16 g_qb16[NHEAD * LQ * DPAD];           // Q·c2 bf16, word-permuted, pad col72=1
__device__ __nv_bfloat16 g_kb16[NHEAD * LQ * DPAD];           // K bf16, word-permuted, pad col72=-moff
__device__ __nv_bfloat16 g_vb16[NHEAD * (LQ / 2) * DPAD * 2]; // V bf16 pair-interleaved, col72=1

// ---------------- helpers ----------------
__device__ __forceinline__ float tf32r(float x) {
    uint32_t u;
    asm("cvt.rna.tf32.f32 %0, %1;" : "=r"(u) : "f"(x));
    return __uint_as_float(u);
}
__device__ __forceinline__ float fexp2(float x) {
    float r;
    asm("ex2.approx.f32 %0, %1;" : "=f"(r) : "f"(x));
    return r;
}
__device__ __forceinline__ uint32_t packbf(float lo, float hi) {
    uint32_t r;
    asm("cvt.rn.bf16x2.f32 %0, %1, %2;" : "=r"(r) : "f"(hi), "f"(lo));
    return r;
}

__device__ __forceinline__ void mma8(float* c, float a0, float a1, float a2, float a3,
                                     float b0, float b1) {
    asm volatile(
        "mma.sync.aligned.m16n8k8.row.col.f32.tf32.tf32.f32 "
        "{%0,%1,%2,%3}, {%4,%5,%6,%7}, {%8,%9}, {%0,%1,%2,%3};\n"
        : "+f"(c[0]), "+f"(c[1]), "+f"(c[2]), "+f"(c[3])
        : "r"(__float_as_uint(a0)), "r"(__float_as_uint(a1)),
          "r"(__float_as_uint(a2)), "r"(__float_as_uint(a3)),
          "r"(__float_as_uint(b0)), "r"(__float_as_uint(b1)));
}
__device__ __forceinline__ void mma16b(float* c, uint32_t a0, uint32_t a1, uint32_t a2,
                                       uint32_t a3, uint32_t b0, uint32_t b1) {
    asm volatile(
        "mma.sync.aligned.m16n8k16.row.col.f32.bf16.bf16.f32 "
        "{%0,%1,%2,%3}, {%4,%5,%6,%7}, {%8,%9}, {%0,%1,%2,%3};\n"
        : "+f"(c[0]), "+f"(c[1]), "+f"(c[2]), "+f"(c[3])
        : "r"(a0), "r"(a1), "r"(a2), "r"(a3), "r"(b0), "r"(b1));
}

__device__ __forceinline__ void cp16(uint32_t dst, const void* src) {
    asm volatile("cp.async.cg.shared.global [%0], [%1], 16;\n" :: "r"(dst), "l"(src));
}
__device__ __forceinline__ void cp_commit() { asm volatile("cp.async.commit_group;\n"); }
__device__ __forceinline__ void cp_wait0()  { asm volatile("cp.async.wait_group 0;\n"); }
__device__ __forceinline__ void cp_wait1()  { asm volatile("cp.async.wait_group 1;\n"); }

// ---------------- prep: round weights + pads + bias2 ----------------
#define W1 (DMODEL * TD)
#define W2 (DMODEL * DMODEL)
#define W3 (OUTC * DMODEL)
#define W1Q (W1 / 4)
#define W2Q (W2 / 4)
#define W3Q (W3 / 4)
#define PADN (2 * NHEAD * LQ * 4)
#define PADV (NHEAD * (LQ / 2) * 8 * 2)
__global__ void prep_weights(const float* __restrict__ w_qkv,
                             const float* __restrict__ w_out,
                             const float* __restrict__ conv_w,
                             const float* __restrict__ b_out) {
    int idx = blockIdx.x * blockDim.x + threadIdx.x;
    if (idx < W1Q + W2Q + W3Q) {
        const float* src;
        float* dst;
        int i;
        if (idx < W1Q) { src = w_qkv; dst = g_wq; i = idx; }
        else if (idx < W1Q + W2Q) { src = w_out; dst = g_wo; i = idx - W1Q; }
        else { src = conv_w; dst = g_cw; i = idx - W1Q - W2Q; }
        float4 v = ((const float4*)src)[i];
        v.x = tf32r(v.x); v.y = tf32r(v.y); v.z = tf32r(v.z); v.w = tf32r(v.w);
        ((float4*)dst)[i] = v;
    } else if (idx < W1Q + W2Q + W3Q + PADN) {
        int j = idx - (W1Q + W2Q + W3Q);
        int arr = j >> 17;
        int rem = j & 0x1FFFF;
        int hr = rem >> 2;
        int pi = rem & 3;
        const float c2 = 1.4426950408889634f * rsqrtf((float)DHEAD);
        uint32_t val = 0;
        if (pi == 0)
            val = arr ? packbf(-64.0f * c2, 0.0f) : packbf(1.0f, 0.0f);
        uint32_t* dst = (uint32_t*)(arr ? g_kb16 : g_qb16);
        dst[(size_t)hr * 40 + 33 + 2 * pi] = val;
    } else if (idx < W1Q + W2Q + W3Q + PADN + PADV) {
        int j = idx - (W1Q + W2Q + W3Q + PADN);
        int kph = j >> 4;
        int rem = j & 15;
        int d = 72 + (rem >> 1);
        int par = rem & 1;
        g_vb16[(size_t)kph * 160 + d * 2 + par] =
            __float2bfloat16_rn(d == 72 ? 1.0f : 0.0f);
    } else if (idx < W1Q + W2Q + W3Q + PADN + PADV + OUTC) {
        int j = idx - (W1Q + W2Q + W3Q + PADN + PADV);
        float s = 0.f;
        const float* cwr = conv_w + (size_t)j * DMODEL;
        for (int k = 0; k < DMODEL; k++) s += b_out[k] * cwr[k];
        g_b2[j] = s;
    }
}

// ---------------- unfold 3x3 stride 2 pad 1 (rounded) ----------------
__global__ void unfold_kernel(const float* __restrict__ fea) {
    int idx = blockIdx.x * blockDim.x + threadIdx.x;
    if (idx >= LQ * DMODEL) return;
    int l = idx / DMODEL;
    int d = idx - l * DMODEL;
    int c = d / 9;
    int k = d - c * 9;
    int ki = k / 3, kj = k - ki * 3;
    int oh = l >> 6, ow = l & 63;
    int ih = 2 * oh + ki - 1;
    int iw = 2 * ow + kj - 1;
    float v = 0.f;
    if ((unsigned)ih < 128u && (unsigned)iw < 128u)
        v = fea[(c * 128 + ih) * 128 + iw];
    g_x[idx] = tf32r(v);
}

// ---------------- TF32 GEMM ----------------
// EPI: 2 = silu(v + bias + R) transposed store; 3 = fused bf16 qkv epilogue;
//      4 = plain tf32r store
#define GEMM_SMEM_BYTES ((3 * 128 * 36 + 3 * 2304) * 4)

template <int TRANSB, int EPI>
__global__ __launch_bounds__(256)
void gemm_tf32(const float* __restrict__ A, const float* __restrict__ B,
               const float* __restrict__ bias, const float* __restrict__ R,
               float* __restrict__ C, int M, int N, int K) {
    extern __shared__ float sm[];
    float* As = sm;
    float* Bs = sm + 3 * 128 * 36;
    const uint32_t as_b = (uint32_t)__cvta_generic_to_shared(As);
    const uint32_t bs_b = (uint32_t)__cvta_generic_to_shared(Bs);

    const int tid = threadIdx.x;
    const int lane = tid & 31;
    const int wid = tid >> 5;
    const int g = lane >> 2, t = lane & 3;
    const int wm = wid >> 1, wn = wid & 1;
    const int m0 = blockIdx.y * 128, n0 = blockIdx.x * 64;

    float acc[2][4][4] = {};

    auto loadTiles = [&](int k0, int buf) {
        #pragma unroll
        for (int i = 0; i < 4; i++) {
            int idx = tid + i * 256;
            int r = idx >> 3, c = (idx & 7) * 4;
            cp16(as_b + (uint32_t)(buf * 128 * 36 + r * 36 + c) * 4,
                 &A[(size_t)(m0 + r) * K + k0 + c]);
        }
        if (!TRANSB) {
            #pragma unroll
            for (int i = 0; i < 2; i++) {
                int idx = tid + i * 256;
                int r = idx >> 4, c = (idx & 15) * 4;
                cp16(bs_b + (uint32_t)(buf * 2304 + r * 72 + c) * 4,
                     &B[(size_t)(k0 + r) * N + n0 + c]);
            }
        } else {
            #pragma unroll
            for (int i = 0; i < 2; i++) {
                int idx = tid + i * 256;
                int r = idx >> 3, c = (idx & 7) * 4;
                cp16(bs_b + (uint32_t)(buf * 2304 + r * 36 + c) * 4,
                     &B[(size_t)(n0 + r) * K + k0 + c]);
            }
        }
        cp_commit();
    };

    const int nk = K / 32;
    loadTiles(0, 0);
    loadTiles(32, 1);

    int buf = 0;
    for (int ik = 0; ik < nk; ik++) {
        if (ik == nk - 1) cp_wait0(); else cp_wait1();
        __syncthreads();
        if (ik + 2 < nk) {
            int nb = buf + 2; if (nb >= 3) nb -= 3;
            loadTiles((ik + 2) * 32, nb);
        }

        const float* as = As + buf * 128 * 36;
        const float* bs = Bs + buf * 2304;

        #pragma unroll
        for (int kk = 0; kk < 4; kk++) {
            const int kc = kk * 8;
            float a[2][4], b[4][2];
            #pragma unroll
            for (int am = 0; am < 2; am++) {
                int r = wm * 32 + am * 16;
                a[am][0] = as[(r + g) * 36 + kc + t];
                a[am][1] = as[(r + g + 8) * 36 + kc + t];
                a[am][2] = as[(r + g) * 36 + kc + t + 4];
                a[am][3] = as[(r + g + 8) * 36 + kc + t + 4];
            }
            #pragma unroll
            for (int j = 0; j < 4; j++) {
                int cb = wn * 32 + 8 * j + g;
                if (!TRANSB) {
                    b[j][0] = bs[(kc + t) * 72 + cb];
                    b[j][1] = bs[(kc + t + 4) * 72 + cb];
                } else {
                    b[j][0] = bs[cb * 36 + kc + t];
                    b[j][1] = bs[cb * 36 + kc + t + 4];
                }
            }
            #pragma unroll
            for (int am = 0; am < 2; am++)
                #pragma unroll
                for (int j = 0; j < 4; j++)
                    mma8(acc[am][j], a[am][0], a[am][1], a[am][2], a[am][3],
                         b[j][0], b[j][1]);
        }
        __syncthreads();
        if (++buf == 3) buf = 0;
    }

    const float qs = 1.4426950408889634f * rsqrtf((float)DHEAD);

    #pragma unroll
    for (int am = 0; am < 2; am++) {
        int r0 = m0 + wm * 32 + am * 16 + g;
        int r1 = r0 + 8;
        #pragma unroll
        for (int j = 0; j < 4; j++) {
            int c0 = n0 + wn * 32 + 8 * j + 2 * t;
            float v00 = acc[am][j][0], v01 = acc[am][j][1];
            float v10 = acc[am][j][2], v11 = acc[am][j][3];
            if (EPI == 4) {
                if (r0 < M) {
                    C[(size_t)r0 * N + c0]     = tf32r(v00);
                    C[(size_t)r0 * N + c0 + 1] = tf32r(v01);
                }
                if (r1 < M) {
                    C[(size_t)r1 * N + c0]     = tf32r(v10);
                    C[(size_t)r1 * N + c0 + 1] = tf32r(v11);
                }
            } else if (EPI == 2) {
                float y00 = v00 + bias[c0]     + R[(size_t)r0 * N + c0];
                float y01 = v01 + bias[c0 + 1] + R[(size_t)r0 * N + c0 + 1];
                float y10 = v10 + bias[c0]     + R[(size_t)r1 * N + c0];
                float y11 = v11 + bias[c0 + 1] + R[(size_t)r1 * N + c0 + 1];
                C[(size_t)(c0)     * M + r0] = y00 / (1.f + __expf(-y00));
                C[(size_t)(c0 + 1) * M + r0] = y01 / (1.f + __expf(-y01));
                C[(size_t)(c0)     * M + r1] = y10 / (1.f + __expf(-y10));
                C[(size_t)(c0 + 1) * M + r1] = y11 / (1.f + __expf(-y11));
            } else {  // EPI == 3: qkv -> bf16 Q/K (word-pair permuted) + V (interleaved)
                float x00 = v00 + bias[c0], x01 = v01 + bias[c0 + 1];
                float x10 = v10 + bias[c0], x11 = v11 + bias[c0 + 1];
                int s = c0 / DMODEL;
                int n2 = c0 - s * DMODEL;
                int hh = n2 / DHEAD;
                int d = n2 - hh * DHEAD;
                if (s < 2) {
                    if (s == 0) { x00 *= qs; x01 *= qs; x10 *= qs; x11 *= qs; }
                    int w = d >> 1, ka = w >> 3, p = w & 7;
                    int wp = 8 * ka + ((p < 4) ? 2 * p : 2 * (p - 4) + 1);
                    uint32_t* dst = (uint32_t*)(s == 0 ? g_qb16 : g_kb16);
                    dst[((size_t)hh * LQ + r0) * 40 + wp] = packbf(x00, x01);
                    dst[((size_t)hh * LQ + r1) * 40 + wp] = packbf(x10, x11);
                } else {
                    __nv_bfloat16* dst = g_vb16;
                    size_t b0i = ((size_t)hh * (LQ / 2) + (r0 >> 1)) * 160 + (r0 & 1);
                    size_t b1i = ((size_t)hh * (LQ / 2) + (r1 >> 1)) * 160 + (r1 & 1);
                    dst[b0i + d * 2]       = __float2bfloat16_rn(x00);
                    dst[b0i + (d + 1) * 2] = __float2bfloat16_rn(x01);
                    dst[b1i + d * 2]       = __float2bfloat16_rn(x10);
                    dst[b1i + (d + 1) * 2] = __float2bfloat16_rn(x11);
                }
            }
        }
    }
}

// ---------------- flash attention: KB=64, folded softmax (R13, proven) ----------
#define QROWS 64
#define KB    64
#define QH_BYTES (64 * 160)
#define KH_BYTES (64 * 160)
#define VP_BYTES (32 * 352)
#define ATTN_SMEM_BYTES (QH_BYTES + 2 * KH_BYTES + 2 * VP_BYTES)

__global__ __launch_bounds__(128, 4)
void attn_bf16(const __nv_bfloat16* __restrict__ qb16,
               const __nv_bfloat16* __restrict__ kb16,
               const __nv_bfloat16* __restrict__ vb16,
               float* __restrict__ o_out) {
    extern __shared__ char smc[];
    const uint32_t sm_b = (uint32_t)__cvta_generic_to_shared(smc);
    const uint32_t qh_b = sm_b;
    const uint32_t kh_b = sm_b + QH_BYTES;
    const uint32_t vp_b = kh_b + 2 * KH_BYTES;
    const uint32_t* qw = (const uint32_t*)smc;
    const uint32_t* kw = (const uint32_t*)(smc + QH_BYTES);
    const uint32_t* vw = (const uint32_t*)(smc + QH_BYTES + 2 * KH_BYTES);

    const int tid = threadIdx.x;
    const int lane = tid & 31;
    const int wid = tid >> 5;
    const int g = lane >> 2, t = lane & 3;
    const int h = blockIdx.y;
    const int q0 = blockIdx.x * QROWS;
    const int wr = wid * 16;

    auto loadKV = [&](int kb, int buf) {
        #pragma unroll
        for (int s = 0; s < 10; s++) {
            int idx = tid + s * 128;
            if (idx < 640) {
                int r = idx / 10, c = idx - r * 10;
                const __nv_bfloat16* src =
                    kb16 + ((size_t)h * LQ + kb * KB + r) * DPAD + c * 8;
                cp16(kh_b + (uint32_t)(buf * KH_BYTES + r * 160 + c * 16), src);
            } else {
                int vi = idx - 640;
                int vr = vi / 20, vc = vi - vr * 20;
                const __nv_bfloat16* src =
                    vb16 + ((size_t)h * (LQ / 2) + kb * 32 + vr) * (DPAD * 2) + vc * 8;
                cp16(vp_b + (uint32_t)(buf * VP_BYTES + vr * 352 + vc * 16), src);
            }
        }
        cp_commit();
    };

    #pragma unroll
    for (int s = 0; s < 5; s++) {
        int idx = tid + s * 128;
        int r = idx / 10, c = idx - r * 10;
        const __nv_bfloat16* src = qb16 + ((size_t)h * LQ + q0 + r) * DPAD + c * 8;
        cp16(qh_b + (uint32_t)(r * 160 + c * 16), src);
    }
    loadKV(0, 0);

    float oacc[10][4] = {};

    for (int kb = 0; kb < LQ / KB; kb++) {
        cp_wait0();
        __syncthreads();
        if (kb + 1 < LQ / KB) loadKV(kb + 1, (kb + 1) & 1);

        const uint32_t* kwb = kw + (kb & 1) * (KH_BYTES / 4);
        const uint32_t* vwb = vw + (kb & 1) * (VP_BYTES / 4);

        #pragma unroll
        for (int half = 0; half < 2; half++) {
            const uint32_t* kh = kwb + half * 32 * 40;
            const uint32_t* vh = vwb + half * 16 * 88;

            float sc[4][4] = {};
            #pragma unroll
            for (int ka = 0; ka < 5; ka++) {
                const int wo = 8 * ka + 2 * t;
                uint2 qA = *(const uint2*)(qw + (wr + g) * 40 + wo);
                uint2 qB = *(const uint2*)(qw + (wr + g + 8) * 40 + wo);
                #pragma unroll
                for (int j = 0; j < 4; j++) {
                    uint2 kb2 = *(const uint2*)(kh + (8 * j + g) * 40 + wo);
                    mma16b(sc[j], qA.x, qB.x, qA.y, qB.y, kb2.x, kb2.y);
                }
            }

            #pragma unroll
            for (int j = 0; j < 4; j++) {
                sc[j][0] = fexp2(sc[j][0]);
                sc[j][1] = fexp2(sc[j][1]);
                sc[j][2] = fexp2(sc[j][2]);
                sc[j][3] = fexp2(sc[j][3]);
            }

            #pragma unroll
            for (int ka2 = 0; ka2 < 2; ka2++) {
                uint32_t pa0 = packbf(sc[2 * ka2][0],     sc[2 * ka2][1]);
                uint32_t pa1 = packbf(sc[2 * ka2][2],     sc[2 * ka2][3]);
                uint32_t pa2 = packbf(sc[2 * ka2 + 1][0], sc[2 * ka2 + 1][1]);
                uint32_t pa3 = packbf(sc[2 * ka2 + 1][2], sc[2 * ka2 + 1][3]);
                const uint32_t* v0p = vh + (8 * ka2 + t) * 88 + g;
                const uint32_t* v1p = vh + (8 * ka2 + 4 + t) * 88 + g;
                #pragma unroll
                for (int j2 = 0; j2 < 10; j2++) {
                    mma16b(oacc[j2], pa0, pa1, pa2, pa3, v0p[8 * j2], v1p[8 * j2]);
                }
            }
        }
    }

    float l0 = __shfl_sync(0xffffffffu, oacc[9][0], lane & 28);
    float l1 = __shfl_sync(0xffffffffu, oacc[9][2], lane & 28);
    float i0 = 1.f / l0, i1 = 1.f / l1;
    float* d0 = o_out + (size_t)(q0 + wr + g) * DMODEL + h * DHEAD;
    float* d1 = d0 + 8 * (size_t)DMODEL;
    #pragma unroll
    for (int j2 = 0; j2 < 9; j2++) {
        d0[8 * j2 + 2 * t]     = tf32r(oacc[j2][0] * i0);
        d0[8 * j2 + 2 * t + 1] = tf32r(oacc[j2][1] * i0);
        d1[8 * j2 + 2 * t]     = tf32r(oacc[j2][2] * i1);
        d1[8 * j2 + 2 * t + 1] = tf32r(oacc[j2][3] * i1);
    }
}

// ---------------- launch ----------------
extern "C" void kernel_launch(void* const* d_in, const int* in_sizes, int n_in,
                              void* d_out, int out_size) {
    const float* fea    = (const float*)d_in[0];
    const float* w_qkv  = (const float*)d_in[1];
    const float* b_qkv  = (const float*)d_in[2];
    const float* w_out  = (const float*)d_in[3];
    const float* b_out  = (const float*)d_in[4];
    const float* conv_w = (const float*)d_in[5];
    float* out = (float*)d_out;

    float *px, *po, *pz, *pm1, *pb2, *pwq, *pwo, *pcw;
    __nv_bfloat16 *pqb, *pkb, *pvb;
    cudaGetSymbolAddress((void**)&px,  g_x);
    cudaGetSymbolAddress((void**)&po,  g_o);
    cudaGetSymbolAddress((void**)&pz,  g_z);
    cudaGetSymbolAddress((void**)&pm1, g_m1t);
    cudaGetSymbolAddress((void**)&pb2, g_b2);
    cudaGetSymbolAddress((void**)&pwq, g_wq);
    cudaGetSymbolAddress((void**)&pwo, g_wo);
    cudaGetSymbolAddress((void**)&pcw, g_cw);
    cudaGetSymbolAddress((void**)&pqb, g_qb16);
    cudaGetSymbolAddress((void**)&pkb, g_kb16);
    cudaGetSymbolAddress((void**)&pvb, g_vb16);

    cudaFuncSetAttribute(gemm_tf32<0, 3>, cudaFuncAttributeMaxDynamicSharedMemorySize, GEMM_SMEM_BYTES);
    cudaFuncSetAttribute(gemm_tf32<1, 4>, cudaFuncAttributeMaxDynamicSharedMemorySize, GEMM_SMEM_BYTES);
    cudaFuncSetAttribute(gemm_tf32<1, 2>, cudaFuncAttributeMaxDynamicSharedMemorySize, GEMM_SMEM_BYTES);
    cudaFuncSetAttribute(attn_bf16, cudaFuncAttributeMaxDynamicSharedMemorySize, ATTN_SMEM_BYTES);

    // 0) round weights + pads + bias2, 1) unfold
    prep_weights<<<(W1Q + W2Q + W3Q + PADN + PADV + OUTC + 255) / 256, 256>>>(
        w_qkv, w_out, conv_w, b_out);
    unfold_kernel<<<(LQ * DMODEL + 255) / 256, 256>>>(fea);

    // 2) qkv GEMM with fused bf16 Q/K/V epilogue
    gemm_tf32<0, 3><<<dim3(TD / 64, LQ / 128), 256, GEMM_SMEM_BYTES>>>(
        px, pwq, b_qkv, nullptr, nullptr, LQ, TD, DMODEL);

    // 2.1) M1T[n][j] = sum_k cw[n][k]*wo[j][k]  -> TRANSB (B rows = wo rows)
    gemm_tf32<1, 4><<<dim3(DMODEL / 64, 1), 256, GEMM_SMEM_BYTES>>>(
        pcw, pwo, nullptr, nullptr, pm1, OUTC, DMODEL, DMODEL);

    // 2.2) z = x @ cw^T   [4096, 128]
    gemm_tf32<1, 4><<<dim3(OUTC / 64, LQ / 128), 256, GEMM_SMEM_BYTES>>>(
        px, pcw, nullptr, nullptr, pz, LQ, OUTC, DMODEL);

    // 3) attention
    attn_bf16<<<dim3(LQ / QROWS, NHEAD), 128, ATTN_SMEM_BYTES>>>(pqb, pkb, pvb, po);

    // 4) out = silu(o @ M1T^T + z + bias2), stored [128, 4096]
    gemm_tf32<1, 2><<<dim3(OUTC / 64, LQ / 128), 256, GEMM_SMEM_BYTES>>>(
        po, pm1, pb2, pz, out, LQ, OUTC, DMODEL);
}